// round 7
// baseline (speedup 1.0000x reference)
#include <cuda_runtime.h>
#include <cstdint>

// ERGCNLayer: out[n] = h[n] + sum_{k: dst[k]=n} ( h[src[k]]*weight[rel[k]] + e[k]*attention[rel[k]] )
// N=100000, E=1600000, D=64, R=200
// d_in: 0=h[N,64]f32 1=e[E,64]f32 2=weight[R,64]f32 3=attention[R,64]f32
//       4=src[E]i32 5=dst[E]i32 6=rel[E]i32 ; out f32[N,64]

#define D 64
#define VEC_PER_ROW (D / 4)     // 16 float4 per row
#define TPE 8                   // threads per edge (2 float4 each = 32B of row)
#define EPT 2                   // edges per thread-group iteration
#define BLOCK 512
#define GROUPS_PER_BLOCK (BLOCK / TPE)   // 64
#define GRID 304

// out = h (residual init)
__global__ void init_out_kernel(const float4* __restrict__ h4,
                                float4* __restrict__ out4, int n4) {
    int i = blockIdx.x * blockDim.x + threadIdx.x;
    if (i < n4) out4[i] = h4[i];
}

__global__ void __launch_bounds__(BLOCK, 1)
edge_scatter_kernel(const float4* __restrict__ h4,
                    const float4* __restrict__ e4,
                    const float4* __restrict__ w4,
                    const float4* __restrict__ a4,
                    const int* __restrict__ src,
                    const int* __restrict__ dst,
                    const int* __restrict__ rel,
                    float* __restrict__ out,
                    int E, int R) {
    // Dynamic smem: w table then a table, R*16 float4 each.
    extern __shared__ float4 smem[];
    float4* w_s = smem;            // [R * VEC_PER_ROW]
    float4* a_s = smem + (size_t)R * VEC_PER_ROW;

    // Fill relation tables once per block (reads hit L2; ~102KB per block).
    for (int i = threadIdx.x; i < R * VEC_PER_ROW; i += BLOCK) {
        w_s[i] = __ldg(w4 + i);
        a_s[i] = __ldg(a4 + i);
    }
    __syncthreads();

    int sub = threadIdx.x & (TPE - 1);                   // 32B chunk index
    long long g0     = (long long)blockIdx.x * GROUPS_PER_BLOCK + (threadIdx.x / TPE);
    long long stride = (long long)gridDim.x * GROUPS_PER_BLOCK;
    long long ngroups = ((long long)E + EPT - 1) / EPT;

    for (long long g = g0; g < ngroups; g += stride) {
        long long ebase = g * EPT;

        // Phase 1: independent global loads (indices + streaming e)
        int s[EPT], d[EPT], r[EPT];
        float4 ev0[EPT], ev1[EPT];
        bool valid[EPT];
#pragma unroll
        for (int k = 0; k < EPT; k++) {
            long long edge = ebase + k;
            valid[k] = edge < E;
            long long ce = valid[k] ? edge : 0;
            s[k] = __ldg(src + ce);
            d[k] = __ldg(dst + ce);
            r[k] = __ldg(rel + ce);
            ev0[k] = __ldcs(e4 + ce * VEC_PER_ROW + sub);        // single-touch stream
            ev1[k] = __ldcs(e4 + ce * VEC_PER_ROW + sub + TPE);
        }

        // Phase 2: dependent h gather (L2-resident)
        float4 hv0[EPT], hv1[EPT];
#pragma unroll
        for (int k = 0; k < EPT; k++) {
            long long hb = (long long)s[k] * VEC_PER_ROW;
            hv0[k] = __ldg(h4 + hb + sub);
            hv1[k] = __ldg(h4 + hb + sub + TPE);
        }

        // Phase 3: w/a from shared memory (off the L1tex path) + compute + RED
#pragma unroll
        for (int k = 0; k < EPT; k++) {
            if (!valid[k]) continue;
            int rb = r[k] * VEC_PER_ROW;
            float4 wv0 = w_s[rb + sub];
            float4 wv1 = w_s[rb + sub + TPE];
            float4 av0 = a_s[rb + sub];
            float4 av1 = a_s[rb + sub + TPE];

            float m0x = fmaf(hv0[k].x, wv0.x, ev0[k].x * av0.x);
            float m0y = fmaf(hv0[k].y, wv0.y, ev0[k].y * av0.y);
            float m0z = fmaf(hv0[k].z, wv0.z, ev0[k].z * av0.z);
            float m0w = fmaf(hv0[k].w, wv0.w, ev0[k].w * av0.w);
            float m1x = fmaf(hv1[k].x, wv1.x, ev1[k].x * av1.x);
            float m1y = fmaf(hv1[k].y, wv1.y, ev1[k].y * av1.y);
            float m1z = fmaf(hv1[k].z, wv1.z, ev1[k].z * av1.z);
            float m1w = fmaf(hv1[k].w, wv1.w, ev1[k].w * av1.w);

            float* p0 = out + (long long)d[k] * D + sub * 4;
            float* p1 = p0 + TPE * 4;
            asm volatile("red.global.add.v4.f32 [%0], {%1, %2, %3, %4};"
                         :: "l"(p0), "f"(m0x), "f"(m0y), "f"(m0z), "f"(m0w) : "memory");
            asm volatile("red.global.add.v4.f32 [%0], {%1, %2, %3, %4};"
                         :: "l"(p1), "f"(m1x), "f"(m1y), "f"(m1z), "f"(m1w) : "memory");
        }
    }
}

extern "C" void kernel_launch(void* const* d_in, const int* in_sizes, int n_in,
                              void* d_out, int out_size) {
    const float* h  = (const float*)d_in[0];
    const float* e  = (const float*)d_in[1];
    const float* w  = (const float*)d_in[2];
    const float* a  = (const float*)d_in[3];
    const int* src  = (const int*)d_in[4];
    const int* dst  = (const int*)d_in[5];
    const int* rel  = (const int*)d_in[6];
    float* out      = (float*)d_out;

    int E  = in_sizes[4];
    int R  = in_sizes[2] / D;          // 200
    int n4 = out_size / 4;

    init_out_kernel<<<(n4 + 255) / 256, 256>>>((const float4*)h, (float4*)out, n4);

    size_t smem_bytes = (size_t)2 * R * VEC_PER_ROW * sizeof(float4);  // ~102.4 KB
    static bool attr_set = false;
    if (!attr_set) {
        cudaFuncSetAttribute(edge_scatter_kernel,
                             cudaFuncAttributeMaxDynamicSharedMemorySize,
                             (int)smem_bytes);
        attr_set = true;
    }

    edge_scatter_kernel<<<GRID, BLOCK, smem_bytes>>>(
        (const float4*)h, (const float4*)e, (const float4*)w, (const float4*)a,
        src, dst, rel, out, E, R);
}

// round 16
// speedup vs baseline: 1.0277x; 1.0277x over previous
#include <cuda_runtime.h>
#include <cstdint>

// ERGCNLayer: out[n] = h[n] + sum_{k: dst[k]=n} ( h[src[k]]*weight[rel[k]] + e[k]*attention[rel[k]] )
// N=100000, E=1600000, D=64, R=200
// d_in: 0=h[N,64]f32 1=e[E,64]f32 2=weight[R,64]f32 3=attention[R,64]f32
//       4=src[E]i32 5=dst[E]i32 6=rel[E]i32 ; out f32[N,64]
//
// Two-phase dst-clustering (kills the ~820MB atomic-RMW LTS stream):
//   zero   : clear per-node counters + overflow counter
//   build  : bucket edges by dst -> packed int2 {edge, src|rel<<17} slots
//   gather : one warp per node, register accumulation, out = h + acc (plain write)
//   fixup  : replay rare CAP-overflow edges with vector REDs (expected 0 iterations)

#define D 64
#define NN 100000
#define CAP 64               // in-degree slots; Poisson(16) => P(>64) ~ 0
#define MAXOVF 8192
#define F2_PER_ROW 32
#define SRC_BITS 17          // 100000 < 2^17
#define SRC_MASK ((1 << SRC_BITS) - 1)

__device__ int  g_cnt[NN];
__device__ int2 g_lst[(size_t)NN * CAP];   // {edge, src | rel<<17}
__device__ int  g_ovf_cnt;
__device__ int  g_ovf[MAXOVF];             // overflow edge ids

__global__ void zero_cnt_kernel(int n) {
    int i = blockIdx.x * blockDim.x + threadIdx.x;
    if (i < n) g_cnt[i] = 0;
    if (i == 0) g_ovf_cnt = 0;
}

__global__ void build_kernel(const int* __restrict__ src,
                             const int* __restrict__ dst,
                             const int* __restrict__ rel,
                             int E) {
    int k = blockIdx.x * blockDim.x + threadIdx.x;
    if (k >= E) return;
    int d = dst[k];
    int pos = atomicAdd(&g_cnt[d], 1);
    if (pos < CAP) {
        g_lst[(size_t)d * CAP + pos] = make_int2(k, src[k] | (rel[k] << SRC_BITS));
    } else {
        int op = atomicAdd(&g_ovf_cnt, 1);
        if (op < MAXOVF) g_ovf[op] = k;
        // op >= MAXOVF cannot occur: sum over nodes of (deg-CAP) bounded far below
        // MAXOVF for any plausible skew of E=1.6M over N=100K; counters stay exact.
    }
}

// One warp per node; lane owns 2 columns. out = h + sum(messages), single plain write.
__global__ void __launch_bounds__(256)
gather_kernel(const float2* __restrict__ h2,
              const float2* __restrict__ e2,
              const float2* __restrict__ w2,
              const float2* __restrict__ a2,
              float2* __restrict__ out2, int Nn) {
    int warp = blockIdx.x * (blockDim.x >> 5) + (threadIdx.x >> 5);
    int lane = threadIdx.x & 31;
    if (warp >= Nn) return;

    int deg = g_cnt[warp];
    if (deg > CAP) deg = CAP;
    const int2* lst = g_lst + (size_t)warp * CAP;

    float accx = 0.f, accy = 0.f;
    int i = 0;
    for (; i + 4 <= deg; i += 4) {           // 16 independent row-loads in flight
        int2 t0 = lst[i + 0], t1 = lst[i + 1], t2 = lst[i + 2], t3 = lst[i + 3];
        int s0 = t0.y & SRC_MASK, r0 = t0.y >> SRC_BITS;
        int s1 = t1.y & SRC_MASK, r1 = t1.y >> SRC_BITS;
        int s2 = t2.y & SRC_MASK, r2 = t2.y >> SRC_BITS;
        int s3 = t3.y & SRC_MASK, r3 = t3.y >> SRC_BITS;
        float2 E0 = __ldcs(e2 + (size_t)t0.x * F2_PER_ROW + lane);
        float2 E1 = __ldcs(e2 + (size_t)t1.x * F2_PER_ROW + lane);
        float2 E2 = __ldcs(e2 + (size_t)t2.x * F2_PER_ROW + lane);
        float2 E3 = __ldcs(e2 + (size_t)t3.x * F2_PER_ROW + lane);
        float2 H0 = __ldg(h2 + (size_t)s0 * F2_PER_ROW + lane);
        float2 H1 = __ldg(h2 + (size_t)s1 * F2_PER_ROW + lane);
        float2 H2 = __ldg(h2 + (size_t)s2 * F2_PER_ROW + lane);
        float2 H3 = __ldg(h2 + (size_t)s3 * F2_PER_ROW + lane);
        float2 W0 = __ldg(w2 + (size_t)r0 * F2_PER_ROW + lane);
        float2 W1 = __ldg(w2 + (size_t)r1 * F2_PER_ROW + lane);
        float2 W2 = __ldg(w2 + (size_t)r2 * F2_PER_ROW + lane);
        float2 W3 = __ldg(w2 + (size_t)r3 * F2_PER_ROW + lane);
        float2 A0 = __ldg(a2 + (size_t)r0 * F2_PER_ROW + lane);
        float2 A1 = __ldg(a2 + (size_t)r1 * F2_PER_ROW + lane);
        float2 A2 = __ldg(a2 + (size_t)r2 * F2_PER_ROW + lane);
        float2 A3 = __ldg(a2 + (size_t)r3 * F2_PER_ROW + lane);
        accx = fmaf(H0.x, W0.x, accx); accx = fmaf(E0.x, A0.x, accx);
        accy = fmaf(H0.y, W0.y, accy); accy = fmaf(E0.y, A0.y, accy);
        accx = fmaf(H1.x, W1.x, accx); accx = fmaf(E1.x, A1.x, accx);
        accy = fmaf(H1.y, W1.y, accy); accy = fmaf(E1.y, A1.y, accy);
        accx = fmaf(H2.x, W2.x, accx); accx = fmaf(E2.x, A2.x, accx);
        accy = fmaf(H2.y, W2.y, accy); accy = fmaf(E2.y, A2.y, accy);
        accx = fmaf(H3.x, W3.x, accx); accx = fmaf(E3.x, A3.x, accx);
        accy = fmaf(H3.y, W3.y, accy); accy = fmaf(E3.y, A3.y, accy);
    }
    for (; i < deg; i++) {
        int2 t = lst[i];
        int s = t.y & SRC_MASK, r = t.y >> SRC_BITS;
        float2 Ev = __ldcs(e2 + (size_t)t.x * F2_PER_ROW + lane);
        float2 Hv = __ldg(h2 + (size_t)s * F2_PER_ROW + lane);
        float2 Wv = __ldg(w2 + (size_t)r * F2_PER_ROW + lane);
        float2 Av = __ldg(a2 + (size_t)r * F2_PER_ROW + lane);
        accx = fmaf(Hv.x, Wv.x, accx); accx = fmaf(Ev.x, Av.x, accx);
        accy = fmaf(Hv.y, Wv.y, accy); accy = fmaf(Ev.y, Av.y, accy);
    }

    size_t oidx = (size_t)warp * F2_PER_ROW + lane;
    float2 hrow = __ldg(h2 + oidx);          // residual
    out2[oidx] = make_float2(hrow.x + accx, hrow.y + accy);
}

// Replay overflow edges (expected count 0) with vector REDs on final output.
__global__ void fixup_kernel(const int* __restrict__ src,
                             const int* __restrict__ dst,
                             const int* __restrict__ rel,
                             const float2* __restrict__ h2,
                             const float2* __restrict__ e2,
                             const float2* __restrict__ w2,
                             const float2* __restrict__ a2,
                             float* __restrict__ out) {
    int cnt = g_ovf_cnt;
    if (cnt > MAXOVF) cnt = MAXOVF;
    int warp = threadIdx.x >> 5;             // 8 warps, single block
    int lane = threadIdx.x & 31;
    for (int i = warp; i < cnt; i += 8) {
        int k = g_ovf[i];
        int s = src[k], d = dst[k], r = rel[k];
        float2 Ev = e2[(size_t)k * F2_PER_ROW + lane];
        float2 Hv = h2[(size_t)s * F2_PER_ROW + lane];
        float2 Wv = w2[(size_t)r * F2_PER_ROW + lane];
        float2 Av = a2[(size_t)r * F2_PER_ROW + lane];
        float mx = fmaf(Hv.x, Wv.x, Ev.x * Av.x);
        float my = fmaf(Hv.y, Wv.y, Ev.y * Av.y);
        asm volatile("red.global.add.v2.f32 [%0], {%1, %2};"
                     :: "l"(out + (size_t)d * D + lane * 2), "f"(mx), "f"(my)
                     : "memory");
    }
}

extern "C" void kernel_launch(void* const* d_in, const int* in_sizes, int n_in,
                              void* d_out, int out_size) {
    const float* h  = (const float*)d_in[0];
    const float* e  = (const float*)d_in[1];
    const float* w  = (const float*)d_in[2];
    const float* a  = (const float*)d_in[3];
    const int* src  = (const int*)d_in[4];
    const int* dst  = (const int*)d_in[5];
    const int* rel  = (const int*)d_in[6];
    float* out      = (float*)d_out;

    int E  = in_sizes[4];
    int Nn = out_size / D;

    zero_cnt_kernel<<<(Nn + 255) / 256, 256>>>(Nn);
    build_kernel<<<(E + 255) / 256, 256>>>(src, dst, rel, E);
    int warps_per_block = 256 / 32;
    int blocks = (Nn + warps_per_block - 1) / warps_per_block;
    gather_kernel<<<blocks, 256>>>((const float2*)h, (const float2*)e,
                                   (const float2*)w, (const float2*)a,
                                   (float2*)out, Nn);
    fixup_kernel<<<1, 256>>>(src, dst, rel,
                             (const float2*)h, (const float2*)e,
                             (const float2*)w, (const float2*)a, out);
}